// round 5
// baseline (speedup 1.0000x reference)
#include <cuda_runtime.h>
#include <cuda_fp16.h>
#include <cstdint>

#define BATCH   128
#define INPUTS  65536
#define OUTPUTS 65536
#define TOPK    32

// Scratch (allocation-free rule: __device__ globals)
__device__ __half         g_xTh[(size_t)INPUTS * BATCH];   // 16 MB: x^T [input, batch], fp16
__device__ float          g_tcT[(size_t)OUTPUTS * TOPK];   // 8 MB: top_c^T [o, k]
__device__ unsigned short g_idxT[(size_t)OUTPUTS * TOPK];  // 4 MB: indices^T, u16
__device__ int            g_idx_is64;                      // dtype flag set by k_detect

// ---------------------------------------------------------------------------
// Kernel 0: detect whether top_indices is int64 or int32 (parallel, 1 block).
// Samples 256 int64-words from the first 8 MB (safe under both layouts).
// ---------------------------------------------------------------------------
__global__ void k_detect(const unsigned long long* __restrict__ p) {
    const int i = threadIdx.x;                      // 256 threads
    const int big = (p[(size_t)i * 4096] >= (unsigned long long)INPUTS) ? 1 : 0;
    const int any = __syncthreads_or(big);
    if (i == 0) g_idx_is64 = !any;
}

// ---------------------------------------------------------------------------
// Kernel 1: transpose x [BATCH, INPUTS] -> g_xTh [INPUTS, BATCH] (fp16)
// ---------------------------------------------------------------------------
__global__ __launch_bounds__(256) void k_transpose_x(const float* __restrict__ x) {
    __shared__ float tile[32][33];
    const int tx = threadIdx.x, ty = threadIdx.y;
    const int o_in = blockIdx.x * 32 + tx;
    const int b0   = blockIdx.y * 32;
#pragma unroll
    for (int i = 0; i < 32; i += 8) {
        tile[ty + i][tx] = x[(size_t)(b0 + ty + i) * INPUTS + o_in];
    }
    __syncthreads();
#pragma unroll
    for (int i = 0; i < 32; i += 8) {
        const int o_out = blockIdx.x * 32 + ty + i;
        g_xTh[(size_t)o_out * BATCH + b0 + tx] = __float2half_rn(tile[tx][ty + i]);
    }
}

// ---------------------------------------------------------------------------
// Kernel 2: transpose top_c -> g_tcT [o,k]; top_indices -> g_idxT [o,k] (u16)
// ---------------------------------------------------------------------------
__global__ __launch_bounds__(256) void k_prep(const float* __restrict__ tc,
                                              const void* __restrict__ idx_raw) {
    __shared__ float tct[32][33];
    __shared__ int   ixt[32][33];
    const int tx = threadIdx.x, ty = threadIdx.y;
    const int o_in = blockIdx.x * 32 + tx;
    const int is64 = g_idx_is64;
    const long long* __restrict__ idx64 = (const long long*)idx_raw;
    const int*       __restrict__ idx32 = (const int*)idx_raw;
#pragma unroll
    for (int i = 0; i < 32; i += 8) {
        const int k = ty + i;
        const size_t e = (size_t)k * OUTPUTS + o_in;
        tct[k][tx] = tc[e];
        ixt[k][tx] = (is64 ? (int)idx64[e] : idx32[e]) & (INPUTS - 1);
    }
    __syncthreads();
#pragma unroll
    for (int i = 0; i < 32; i += 8) {
        const int o_out = blockIdx.x * 32 + ty + i;
        g_tcT[(size_t)o_out * TOPK + tx]  = tct[tx][ty + i];
        g_idxT[(size_t)o_out * TOPK + tx] = (unsigned short)ixt[tx][ty + i];
    }
}

// ---------------------------------------------------------------------------
// Kernel 3: main. One warp per output column o.
//   Gathers split into 2x LDG.32 (each exactly one 128B line -> 1 wavefront
//   at the ~1.0 cyc/wf cross-LDG rate, vs 2 wf at 2.07 within-LDG replay
//   rate for LDG.64). Lane l owns batches {2l, 2l+1, 64+2l, 64+2l+1}.
// ---------------------------------------------------------------------------
__global__ __launch_bounds__(256) void k_main(float* __restrict__ out) {
    __shared__ float sm[8][BATCH];            // [o_local][b]
    const int warp = threadIdx.x >> 5;
    const int lane = threadIdx.x & 31;
    const int o    = blockIdx.x * 8 + warp;

    const float c  = g_tcT[(size_t)o * TOPK + lane];         // 128B/warp
    const int   ix = (int)g_idxT[(size_t)o * TOPK + lane];   // 64B/warp

    // warp softmax over the 32 lanes (k dimension), C_SPARSITY = 1.0
    float m = c;
#pragma unroll
    for (int s = 16; s > 0; s >>= 1) m = fmaxf(m, __shfl_xor_sync(0xffffffffu, m, s));
    float e = __expf(c - m);
    float ssum = e;
#pragma unroll
    for (int s = 16; s > 0; s >>= 1) ssum += __shfl_xor_sync(0xffffffffu, ssum, s);
    const float w = e / ssum;

    const char* __restrict__ xbase = (const char*)g_xTh;
    float a0 = 0.f, a1 = 0.f, a2 = 0.f, a3 = 0.f;
#pragma unroll
    for (int k = 0; k < TOPK; k++) {
        const int   ik = __shfl_sync(0xffffffffu, ix, k);
        const float wk = __shfl_sync(0xffffffffu, w, k);
        const uint32_t* row = (const uint32_t*)(xbase + ((size_t)ik << 8));
        const uint32_t r0 = row[lane];        // bytes [lane*4],      line 0 (128B)
        const uint32_t r1 = row[lane + 32];   // bytes [128+lane*4],  line 1 (128B)
        const float2 f01 = __half22float2(*reinterpret_cast<const __half2*>(&r0));
        const float2 f23 = __half22float2(*reinterpret_cast<const __half2*>(&r1));
        a0 = fmaf(wk, f01.x, a0);
        a1 = fmaf(wk, f01.y, a1);
        a2 = fmaf(wk, f23.x, a2);
        a3 = fmaf(wk, f23.y, a3);
    }

    // stage: lane l -> batches 2l,2l+1 and 64+2l,64+2l+1 of column o
    float2* s2 = reinterpret_cast<float2*>(sm[warp]);
    s2[lane]      = make_float2(a0, a1);
    s2[32 + lane] = make_float2(a2, a3);
    __syncthreads();

    // write out: thread t -> b = t/2, 4 consecutive o starting at (t&1)*4
    const int t  = threadIdx.x;
    const int b  = t >> 1;
    const int j  = (t & 1) * 4;
    const int o0 = blockIdx.x * 8;
    const float4 v = make_float4(sm[j + 0][b], sm[j + 1][b], sm[j + 2][b], sm[j + 3][b]);
    *reinterpret_cast<float4*>(&out[(size_t)b * OUTPUTS + o0 + j]) = v;
}

// ---------------------------------------------------------------------------
extern "C" void kernel_launch(void* const* d_in, const int* in_sizes, int n_in,
                              void* d_out, int out_size) {
    const float* x   = (const float*)d_in[0];      // [128, 65536] f32
    const float* tc  = (const float*)d_in[1];      // [32, 65536]  f32
    const void*  idx = d_in[2];                    // [32, 65536]  i64 OR i32 (detected)
    float* out = (float*)d_out;                    // [128, 65536] f32

    dim3 tb(32, 8);
    k_detect<<<1, 256>>>((const unsigned long long*)idx);
    k_transpose_x<<<dim3(INPUTS / 32, BATCH / 32), tb>>>(x);
    k_prep<<<dim3(OUTPUTS / 32, 1), tb>>>(tc, idx);
    k_main<<<OUTPUTS / 8, 256>>>(out);
}

// round 8
// speedup vs baseline: 1.1867x; 1.1867x over previous
#include <cuda_runtime.h>
#include <cuda_fp16.h>
#include <cstdint>

#define BATCH   128
#define INPUTS  65536
#define OUTPUTS 65536
#define TOPK    32

// Scratch (allocation-free rule: __device__ globals)
__device__ __half   g_xTh[(size_t)INPUTS * BATCH];   // 16 MB: x^T [input, batch], fp16
__device__ uint32_t g_pk[(size_t)OUTPUTS * TOPK];    // 8 MB: packed {idx:u16<<16 | w:f16}

// ---------------------------------------------------------------------------
// Kernel 1: transpose x [BATCH, INPUTS] -> g_xTh [INPUTS, BATCH] (fp16)
// ---------------------------------------------------------------------------
__global__ __launch_bounds__(256) void k_transpose_x(const float* __restrict__ x) {
    __shared__ float tile[32][33];
    const int tx = threadIdx.x, ty = threadIdx.y;
    const int o_in = blockIdx.x * 32 + tx;
    const int b0   = blockIdx.y * 32;
#pragma unroll
    for (int i = 0; i < 32; i += 8)
        tile[ty + i][tx] = x[(size_t)(b0 + ty + i) * INPUTS + o_in];
    __syncthreads();
#pragma unroll
    for (int i = 0; i < 32; i += 8)
        g_xTh[(size_t)(blockIdx.x * 32 + ty + i) * BATCH + b0 + tx] =
            __float2half_rn(tile[tx][ty + i]);
}

// ---------------------------------------------------------------------------
// Kernel 2: prep. Softmax over k per output column, pack {idx:u16, w:f16}
// into one u32 per (o,k). Dtype of top_indices self-detected per block.
// ---------------------------------------------------------------------------
__global__ __launch_bounds__(256) void k_prep(const float* __restrict__ tc,
                                              const void*  __restrict__ idx_raw) {
    __shared__ float    tct[32][33];
    __shared__ uint32_t ixt[32][33];
    __shared__ float    red[8][33];
    __shared__ float    cmax[32], cinv[32];

    const int tx = threadIdx.x, ty = threadIdx.y;
    const int tid = ty * 32 + tx;

    // self-detect idx dtype: int64 data has zero high words at odd i32 slots.
    // offsets 1..511 ints (2 KB) are in-bounds under both layouts.
    const int* idx32 = (const int*)idx_raw;
    const int  z     = (idx32[2 * tid + 1] == 0) ? 1 : 0;
    const int  is64  = __syncthreads_and(z);

    const long long* idx64 = (const long long*)idx_raw;
    const int o_in = blockIdx.x * 32 + tx;
#pragma unroll
    for (int i = 0; i < 32; i += 8) {
        const int k = ty + i;
        const size_t e = (size_t)k * OUTPUTS + o_in;
        tct[k][tx] = tc[e];
        ixt[k][tx] = (uint32_t)((is64 ? (int)idx64[e] : idx32[e]) & (INPUTS - 1));
    }
    __syncthreads();

    // softmax over k (column tx); this thread owns k = ty*4 .. ty*4+3
    float m = -1e30f;
#pragma unroll
    for (int j = 0; j < 4; j++) m = fmaxf(m, tct[ty * 4 + j][tx]);
    red[ty][tx] = m;
    __syncthreads();
    if (ty == 0) {
        float mm = red[0][tx];
#pragma unroll
        for (int r = 1; r < 8; r++) mm = fmaxf(mm, red[r][tx]);
        cmax[tx] = mm;
    }
    __syncthreads();
    const float cm = cmax[tx];
    float e4[4]; float s = 0.f;
#pragma unroll
    for (int j = 0; j < 4; j++) { e4[j] = __expf(tct[ty * 4 + j][tx] - cm); s += e4[j]; }
    red[ty][tx] = s;
    __syncthreads();
    if (ty == 0) {
        float ss = 0.f;
#pragma unroll
        for (int r = 0; r < 8; r++) ss += red[r][tx];
        cinv[tx] = 1.f / ss;
    }
    __syncthreads();
    const float inv = cinv[tx];
#pragma unroll
    for (int j = 0; j < 4; j++) {
        const int k = ty * 4 + j;
        const unsigned short h = __half_as_ushort(__float2half_rn(e4[j] * inv));
        ixt[k][tx] = (ixt[k][tx] << 16) | (uint32_t)h;   // own cell only, no race
    }
    __syncthreads();

    // coalesced write: g_pk[o][k], k contiguous across lanes
#pragma unroll
    for (int i = 0; i < 32; i += 8) {
        const int o_out = blockIdx.x * 32 + ty + i;
        g_pk[(size_t)o_out * TOPK + tx] = ixt[tx][ty + i];
    }
}

// ---------------------------------------------------------------------------
// Kernel 3: main. One warp per output column o. Loop body per k:
//   1 SHFL (packed {idx,w}), 1 LDG.64 gather (256B/warp, L2-resident),
//   5 cvt, 4 FFMA. Lane l owns batches 4l..4l+3.
// ---------------------------------------------------------------------------
__global__ __launch_bounds__(256) void k_main(float* __restrict__ out) {
    __shared__ float sm[8][BATCH];            // [o_local][b]
    const int warp = threadIdx.x >> 5;
    const int lane = threadIdx.x & 31;
    const int o    = blockIdx.x * 8 + warp;

    const uint32_t pk = g_pk[(size_t)o * TOPK + lane];   // 128B/warp, whole prologue

    const char* __restrict__ xb = (const char*)g_xTh;
    float a0 = 0.f, a1 = 0.f, a2 = 0.f, a3 = 0.f;
#pragma unroll
    for (int k = 0; k < TOPK; k++) {
        const uint32_t p  = __shfl_sync(0xffffffffu, pk, k);
        const float    wk = __low2float(*reinterpret_cast<const __half2*>(&p)); // w = low f16
        const uint2    r  = *reinterpret_cast<const uint2*>(
                                xb + ((size_t)(p >> 16) << 8) + lane * 8);      // idx = high u16
        const float2 f01 = __half22float2(*reinterpret_cast<const __half2*>(&r.x));
        const float2 f23 = __half22float2(*reinterpret_cast<const __half2*>(&r.y));
        a0 = fmaf(wk, f01.x, a0);
        a1 = fmaf(wk, f01.y, a1);
        a2 = fmaf(wk, f23.x, a2);
        a3 = fmaf(wk, f23.y, a3);
    }

    // stage: lane l owns batches 4l..4l+3 of column o
    reinterpret_cast<float4*>(sm[warp])[lane] = make_float4(a0, a1, a2, a3);
    __syncthreads();

    // write out: thread t -> b = t/2, 4 consecutive o starting at (t&1)*4
    const int t  = threadIdx.x;
    const int b  = t >> 1;
    const int j  = (t & 1) * 4;
    const int o0 = blockIdx.x * 8;
    const float4 v = make_float4(sm[j + 0][b], sm[j + 1][b], sm[j + 2][b], sm[j + 3][b]);
    *reinterpret_cast<float4*>(&out[(size_t)b * OUTPUTS + o0 + j]) = v;
}

// ---------------------------------------------------------------------------
extern "C" void kernel_launch(void* const* d_in, const int* in_sizes, int n_in,
                              void* d_out, int out_size) {
    const float* x   = (const float*)d_in[0];      // [128, 65536] f32
    const float* tc  = (const float*)d_in[1];      // [32, 65536]  f32
    const void*  idx = d_in[2];                    // [32, 65536]  i64 OR i32 (auto)
    float* out = (float*)d_out;                    // [128, 65536] f32

    dim3 tb(32, 8);
    k_transpose_x<<<dim3(INPUTS / 32, BATCH / 32), tb>>>(x);
    k_prep<<<OUTPUTS / 32, tb>>>(tc, idx);
    k_main<<<OUTPUTS / 8, 256>>>(out);
}

// round 10
// speedup vs baseline: 1.2211x; 1.0289x over previous
#include <cuda_runtime.h>
#include <cuda_fp16.h>
#include <cstdint>

#define BATCH   128
#define INPUTS  65536
#define OUTPUTS 65536
#define TOPK    32

// Scratch (allocation-free rule: __device__ globals)
__device__ __half   g_xTh[(size_t)INPUTS * BATCH];   // 16 MB: x^T [input, batch], fp16
__device__ uint32_t g_pk[(size_t)OUTPUTS * TOPK];    // 8 MB: packed {idx:u16<<16 | w:f16}

// ---------------------------------------------------------------------------
// Kernel 1: transpose x [BATCH, INPUTS] -> g_xTh [INPUTS, BATCH] (fp16)
// 64x64 tiles. Loads: float4/lane from gmem (256B coalesced per half-warp),
// unpacked into 4 scalar smem stores (tile row stride 65 floats is not 16B
// aligned -> float4 STS would trap; scalar STS has no alignment hazard).
// Stores: warp per input-row, 32 x half2 = 128B contiguous.
// ---------------------------------------------------------------------------
__global__ __launch_bounds__(256) void k_transpose_x(const float* __restrict__ x) {
    __shared__ float tile[64][65];
    const int w  = threadIdx.x >> 5;
    const int l  = threadIdx.x & 31;
    const int i0 = blockIdx.x * 64;   // input-index base
    const int b0 = blockIdx.y * 64;   // batch base

    // load: 4 passes; each pass covers 16 batch-rows (half-warp per row)
#pragma unroll
    for (int p = 0; p < 4; p++) {
        const int row = p * 16 + 2 * w + (l >> 4);     // batch row in tile
        const int col = (l & 15) * 4;                  // input col in tile
        const float4 v = *reinterpret_cast<const float4*>(
            &x[(size_t)(b0 + row) * INPUTS + i0 + col]);
        tile[row][col + 0] = v.x;
        tile[row][col + 1] = v.y;
        tile[row][col + 2] = v.z;
        tile[row][col + 3] = v.w;
    }
    __syncthreads();

    // store: 8 passes; warp w -> input row q*8+w; lane l -> batches 2l,2l+1
#pragma unroll
    for (int q = 0; q < 8; q++) {
        const int i  = q * 8 + w;
        const __half h0 = __float2half_rn(tile[2 * l][i]);
        const __half h1 = __float2half_rn(tile[2 * l + 1][i]);
        reinterpret_cast<__half2*>(&g_xTh[(size_t)(i0 + i) * BATCH + b0])[l] =
            __halves2half2(h0, h1);
    }
}

// ---------------------------------------------------------------------------
// Kernel 2: prep. Softmax over k per output column, pack {idx:u16, w:f16}
// into one u32 per (o,k). Dtype of top_indices self-detected per block.
// ---------------------------------------------------------------------------
__global__ __launch_bounds__(256) void k_prep(const float* __restrict__ tc,
                                              const void*  __restrict__ idx_raw) {
    __shared__ float    tct[32][33];
    __shared__ uint32_t ixt[32][33];
    __shared__ float    red[8][33];
    __shared__ float    cmax[32], cinv[32];

    const int tx = threadIdx.x, ty = threadIdx.y;
    const int tid = ty * 32 + tx;

    // self-detect idx dtype: int64 data has zero high words at odd i32 slots.
    // offsets 1..511 ints (2 KB) are in-bounds under both layouts.
    const int* idx32 = (const int*)idx_raw;
    const int  z     = (idx32[2 * tid + 1] == 0) ? 1 : 0;
    const int  is64  = __syncthreads_and(z);

    const long long* idx64 = (const long long*)idx_raw;
    const int o_in = blockIdx.x * 32 + tx;
#pragma unroll
    for (int i = 0; i < 32; i += 8) {
        const int k = ty + i;
        const size_t e = (size_t)k * OUTPUTS + o_in;
        tct[k][tx] = tc[e];
        ixt[k][tx] = (uint32_t)((is64 ? (int)idx64[e] : idx32[e]) & (INPUTS - 1));
    }
    __syncthreads();

    // softmax over k (column tx); this thread owns k = ty*4 .. ty*4+3
    float m = -1e30f;
#pragma unroll
    for (int j = 0; j < 4; j++) m = fmaxf(m, tct[ty * 4 + j][tx]);
    red[ty][tx] = m;
    __syncthreads();
    if (ty == 0) {
        float mm = red[0][tx];
#pragma unroll
        for (int r = 1; r < 8; r++) mm = fmaxf(mm, red[r][tx]);
        cmax[tx] = mm;
    }
    __syncthreads();
    const float cm = cmax[tx];
    float e4[4]; float s = 0.f;
#pragma unroll
    for (int j = 0; j < 4; j++) { e4[j] = __expf(tct[ty * 4 + j][tx] - cm); s += e4[j]; }
    red[ty][tx] = s;
    __syncthreads();
    if (ty == 0) {
        float ss = 0.f;
#pragma unroll
        for (int r = 0; r < 8; r++) ss += red[r][tx];
        cinv[tx] = 1.f / ss;
    }
    __syncthreads();
    const float inv = cinv[tx];
#pragma unroll
    for (int j = 0; j < 4; j++) {
        const int k = ty * 4 + j;
        const unsigned short h = __half_as_ushort(__float2half_rn(e4[j] * inv));
        ixt[k][tx] = (ixt[k][tx] << 16) | (uint32_t)h;   // own cell only, no race
    }
    __syncthreads();

    // coalesced write: g_pk[o][k], k contiguous across lanes
#pragma unroll
    for (int i = 0; i < 32; i += 8) {
        const int o_out = blockIdx.x * 32 + ty + i;
        g_pk[(size_t)o_out * TOPK + tx] = ixt[tx][ty + i];
    }
}

// ---------------------------------------------------------------------------
// Kernel 3: main. One warp per output column o. Loop body per k:
//   1 SHFL (packed {idx,w}), 1 LDG.64 gather (256B/warp, L2-resident),
//   5 cvt, 4 FFMA. Lane l owns batches 4l..4l+3.
// ---------------------------------------------------------------------------
__global__ __launch_bounds__(256) void k_main(float* __restrict__ out) {
    __shared__ float sm[8][BATCH];            // [o_local][b]
    const int warp = threadIdx.x >> 5;
    const int lane = threadIdx.x & 31;
    const int o    = blockIdx.x * 8 + warp;

    const uint32_t pk = g_pk[(size_t)o * TOPK + lane];   // 128B/warp, whole prologue

    const char* __restrict__ xb = (const char*)g_xTh;
    float a0 = 0.f, a1 = 0.f, a2 = 0.f, a3 = 0.f;
#pragma unroll
    for (int k = 0; k < TOPK; k++) {
        const uint32_t p  = __shfl_sync(0xffffffffu, pk, k);
        const float    wk = __low2float(*reinterpret_cast<const __half2*>(&p)); // w = low f16
        const uint2    r  = *reinterpret_cast<const uint2*>(
                                xb + ((size_t)(p >> 16) << 8) + lane * 8);      // idx = high u16
        const float2 f01 = __half22float2(*reinterpret_cast<const __half2*>(&r.x));
        const float2 f23 = __half22float2(*reinterpret_cast<const __half2*>(&r.y));
        a0 = fmaf(wk, f01.x, a0);
        a1 = fmaf(wk, f01.y, a1);
        a2 = fmaf(wk, f23.x, a2);
        a3 = fmaf(wk, f23.y, a3);
    }

    // stage: lane l owns batches 4l..4l+3 of column o
    reinterpret_cast<float4*>(sm[warp])[lane] = make_float4(a0, a1, a2, a3);
    __syncthreads();

    // write out: thread t -> b = t/2, 4 consecutive o starting at (t&1)*4
    const int t  = threadIdx.x;
    const int b  = t >> 1;
    const int j  = (t & 1) * 4;
    const int o0 = blockIdx.x * 8;
    const float4 v = make_float4(sm[j + 0][b], sm[j + 1][b], sm[j + 2][b], sm[j + 3][b]);
    *reinterpret_cast<float4*>(&out[(size_t)b * OUTPUTS + o0 + j]) = v;
}

// ---------------------------------------------------------------------------
extern "C" void kernel_launch(void* const* d_in, const int* in_sizes, int n_in,
                              void* d_out, int out_size) {
    const float* x   = (const float*)d_in[0];      // [128, 65536] f32
    const float* tc  = (const float*)d_in[1];      // [32, 65536]  f32
    const void*  idx = d_in[2];                    // [32, 65536]  i64 OR i32 (auto)
    float* out = (float*)d_out;                    // [128, 65536] f32

    dim3 tb(32, 8);
    k_transpose_x<<<dim3(INPUTS / 64, BATCH / 64), 256>>>(x);
    k_prep<<<OUTPUTS / 32, tb>>>(tc, idx);
    k_main<<<OUTPUTS / 8, 256>>>(out);
}